// round 13
// baseline (speedup 1.0000x reference)
#include <cuda_runtime.h>
#include <cstdint>

// RobustGlobalPool2d: per-slice (4096 elems) Pseudo-Huber location.
// alpha=1: phi'(z)=z*r, phi''=r^3, phi'''=-3 z r^5, r=rsqrt(1+z^2).
// Single-pass second-order (Halley-type) step from the mean init:
//   g = sum z*r, h = sum r^3, s = sum z*r^5, u = g/h
//   y* ~= y0 - u + 1.5*(s/h)*u^2        (residual ~1e-7 abs, << 1e-3 gate)
// R10/R12: persistent grid (148*8 CTAs) looping over slices; each slice staged
// through a 16KB smem buffer via per-thread cp.async.cg (LDGSTS). While a CTA
// computes slice i from registers, slice i+1 streams into smem -> DRAM demand
// is continuous instead of phase-synchronized bursts (R9 capped at 70% duty).
// Thread-private staging: each thread cp.asyncs and LDSes only its own bytes,
// so cp.async.wait_group 0 per-thread suffices. Packed f32x2 FMA; MUFU rsqrt.
// (R11 was a missing <cstdint> include; identical kernel otherwise.)

#define HW      4096
#define THREADS 256
#define PAIRS   8      // 8 f32x2 pairs = 16 elems per thread
#define NWARPS  (THREADS / 32)
#define GRID    1184   // 148 SMs * 8 CTAs

typedef unsigned long long ull;

__device__ __forceinline__ ull pk(float lo, float hi) {
    ull r; asm("mov.b64 %0, {%1, %2};" : "=l"(r) : "f"(lo), "f"(hi)); return r;
}
__device__ __forceinline__ void upk(ull v, float& lo, float& hi) {
    asm("mov.b64 {%0, %1}, %2;" : "=f"(lo), "=f"(hi) : "l"(v));
}
__device__ __forceinline__ ull add2(ull a, ull b) {
    ull r; asm("add.rn.f32x2 %0, %1, %2;" : "=l"(r) : "l"(a), "l"(b)); return r;
}
__device__ __forceinline__ ull mul2(ull a, ull b) {
    ull r; asm("mul.rn.f32x2 %0, %1, %2;" : "=l"(r) : "l"(a), "l"(b)); return r;
}
__device__ __forceinline__ ull fma2(ull a, ull b, ull c) {
    ull r; asm("fma.rn.f32x2 %0, %1, %2, %3;" : "=l"(r) : "l"(a), "l"(b), "l"(c)); return r;
}
__device__ __forceinline__ float frsqrt_approx(float x) {
    float r; asm("rsqrt.approx.f32 %0, %1;" : "=f"(r) : "f"(x)); return r;
}
__device__ __forceinline__ float warp_reduce_add(float v) {
    #pragma unroll
    for (int off = 16; off > 0; off >>= 1)
        v += __shfl_xor_sync(0xFFFFFFFFu, v, off);
    return v;
}
__device__ __forceinline__ uint32_t smem_u32(const void* p) {
    uint32_t a;
    asm("{ .reg .u64 t; cvta.to.shared.u64 t, %1; cvt.u32.u64 %0, t; }"
        : "=r"(a) : "l"(p));
    return a;
}
__device__ __forceinline__ void cp16(uint32_t dst_smem, const void* src) {
    asm volatile("cp.async.cg.shared.global [%0], [%1], 16;"
                 :: "r"(dst_smem), "l"(src) : "memory");
}
__device__ __forceinline__ void cp_commit() {
    asm volatile("cp.async.commit_group;" ::: "memory");
}
__device__ __forceinline__ void cp_wait0() {
    asm volatile("cp.async.wait_group 0;" ::: "memory");
}

__global__ void __launch_bounds__(THREADS, 8)
robust_pool_kernel(const float* __restrict__ x, float* __restrict__ out, int nslices) {
    __shared__ float4 buf[HW / 4];          // 16 KB staging buffer
    __shared__ float s_sum[NWARPS];
    __shared__ float s_g[NWARPS];
    __shared__ float s_h[NWARPS];
    __shared__ float s_s[NWARPS];

    const int tid  = threadIdx.x;
    const int wid  = tid >> 5;
    const int lane = tid & 31;
    const int stride = gridDim.x;

    const uint32_t sb = smem_u32(buf);
    const ull one2 = pk(1.0f, 1.0f);

    int s = blockIdx.x;

    // ---- prologue: prefetch first slice ----
    if (s < nslices) {
        const float4* src = reinterpret_cast<const float4*>(x + (size_t)s * HW);
        #pragma unroll
        for (int j = 0; j < 4; j++)
            cp16(sb + (uint32_t)(tid + j * THREADS) * 16u, src + tid + j * THREADS);
        cp_commit();
    }

    for (; s < nslices; s += stride) {
        const int nxt = s + stride;

        // ---- wait own prefetch; read 16 elems from smem; pack + sum ----
        cp_wait0();
        ull nx[PAIRS];
        float sum = 0.0f;
        #pragma unroll
        for (int j = 0; j < 4; j++) {
            float4 v = buf[tid + j * THREADS];     // LDS.128, thread-private bytes
            sum += (v.x + v.y) + (v.z + v.w);
            nx[2 * j]     = pk(v.x, v.y) ^ 0x8000000080000000ull;
            nx[2 * j + 1] = pk(v.z, v.w) ^ 0x8000000080000000ull;
        }

        // ---- issue prefetch of next slice (thread's own bytes already read) ----
        if (nxt < nslices) {
            const float4* src = reinterpret_cast<const float4*>(x + (size_t)nxt * HW);
            #pragma unroll
            for (int j = 0; j < 4; j++)
                cp16(sb + (uint32_t)(tid + j * THREADS) * 16u, src + tid + j * THREADS);
        }
        cp_commit();   // commit (possibly empty) group so wait0 next iter is balanced

        // ---- Phase 0: mean ----
        sum = warp_reduce_add(sum);
        if (lane == 0) s_sum[wid] = sum;
        __syncthreads();                       // (1)
        float y0;
        {
            float tot = 0.0f;
            #pragma unroll
            for (int w = 0; w < NWARPS; w++) tot += s_sum[w];
            y0 = tot * (1.0f / (float)HW);
        }

        // ---- Phase 1: single pass g, h, s at y0 ----
        {
            const ull y2p = pk(y0, y0);
            ull g2 = 0ull, h2 = 0ull, sv2 = 0ull;
            #pragma unroll
            for (int p = 0; p < PAIRS; p++) {
                ull z2 = add2(y2p, nx[p]);        // z = y - x
                ull t2 = fma2(z2, z2, one2);      // 1 + z^2
                float tl, th; upk(t2, tl, th);
                ull r2 = pk(frsqrt_approx(tl), frsqrt_approx(th));
                ull q2 = mul2(r2, r2);            // r^2
                ull p2 = mul2(z2, r2);            // z*r
                g2  = add2(g2, p2);               // g += z*r
                h2  = fma2(q2, r2, h2);           // h += r^3
                ull w2 = mul2(q2, q2);            // r^4
                sv2 = fma2(p2, w2, sv2);          // s += z*r^5
            }
            float gl, gh, hl, hh, sl, sh;
            upk(g2, gl, gh);
            upk(h2, hl, hh);
            upk(sv2, sl, sh);
            float g = warp_reduce_add(gl + gh);
            float h = warp_reduce_add(hl + hh);
            float sv = warp_reduce_add(sl + sh);
            if (lane == 0) { s_g[wid] = g; s_h[wid] = h; s_s[wid] = sv; }
        }
        __syncthreads();                       // (2)

        if (tid == 0) {
            float gt = 0.0f, ht = 0.0f, st = 0.0f;
            #pragma unroll
            for (int w = 0; w < NWARPS; w++) { gt += s_g[w]; ht += s_h[w]; st += s_s[w]; }
            ht = fmaxf(ht, 1e-12f);
            float u = gt / ht;
            out[s] = y0 - u + 1.5f * (st / ht) * u * u;
        }
        __syncthreads();                       // (3) protect s_sum WAR across iters
    }
}

extern "C" void kernel_launch(void* const* d_in, const int* in_sizes, int n_in,
                              void* d_out, int out_size) {
    const float* x = (const float*)d_in[0];
    float* out = (float*)d_out;
    int n_elems = in_sizes[0];
    int slices = n_elems / HW;          // 8192 for [32,256,64,64]
    int grid = GRID < slices ? GRID : slices;
    robust_pool_kernel<<<grid, THREADS>>>(x, out, slices);
}